// round 1
// baseline (speedup 1.0000x reference)
#include <cuda_runtime.h>

// out[b,c] = dot(x[b,c,:HW], weight[c,:HW]) + bias[c]
// B = 512, C = 512, HW = 784 (float32 everywhere)
// Pure HBM-streaming problem: ~822 MB of x read once.

#define B_DIM 512
#define C_DIM 512
#define HW_DIM 784
#define HW_VEC4 (HW_DIM / 4)   // 196 float4 per row

__global__ __launch_bounds__(256) void scalar_mapping_kernel(
    const float* __restrict__ x,
    const float* __restrict__ weight,
    const float* __restrict__ bias,
    float* __restrict__ out)
{
    const int warp = (blockIdx.x * blockDim.x + threadIdx.x) >> 5;  // row id = b*C + c
    const int lane = threadIdx.x & 31;

    if (warp >= B_DIM * C_DIM) return;

    const int c = warp & (C_DIM - 1);

    const float4* __restrict__ xr =
        reinterpret_cast<const float4*>(x + (size_t)warp * HW_DIM);
    const float4* __restrict__ wr =
        reinterpret_cast<const float4*>(weight + (size_t)c * HW_DIM);

    float sum = 0.0f;

    // 196 float4 per row; 32 lanes -> 6 full iterations + 1 partial (lanes 0-3)
    #pragma unroll
    for (int i = 0; i < 7; ++i) {
        const int idx = lane + i * 32;
        if (idx < HW_VEC4) {
            // x: streamed once, bypass-ish caching (.cs) to keep L2 for weight
            const float4 xv = __ldcs(&xr[idx]);
            const float4 wv = __ldg(&wr[idx]);
            sum = fmaf(xv.x, wv.x, sum);
            sum = fmaf(xv.y, wv.y, sum);
            sum = fmaf(xv.z, wv.z, sum);
            sum = fmaf(xv.w, wv.w, sum);
        }
    }

    // Warp butterfly reduce
    #pragma unroll
    for (int off = 16; off > 0; off >>= 1)
        sum += __shfl_xor_sync(0xFFFFFFFFu, sum, off);

    if (lane == 0)
        out[warp] = sum + __ldg(&bias[c]);
}

extern "C" void kernel_launch(void* const* d_in, const int* in_sizes, int n_in,
                              void* d_out, int out_size)
{
    const float* x      = (const float*)d_in[0];
    const float* weight = (const float*)d_in[1];
    const float* bias   = (const float*)d_in[2];
    float* out          = (float*)d_out;

    // One warp per (b,c) row: B*C warps = 262144 warps -> 32 warps/1024... use 256 thr/blk
    const int total_warps   = B_DIM * C_DIM;
    const int warps_per_blk = 256 / 32;
    const int blocks        = total_warps / warps_per_blk;  // 32768

    scalar_mapping_kernel<<<blocks, 256>>>(x, weight, bias, out);
}